// round 14
// baseline (speedup 1.0000x reference)
#include <cuda_runtime.h>
#include <cuda_fp16.h>
#include <cstdint>
#include <cstddef>

#define BATCH 2
#define CC 128
#define HW 4096
#define HEADS 4
// 32^-0.5 * log2(e): softmax in base-2
#define SCALE2 0.25500526764086436f

// ---------------- scratch ----------------
__device__ float g_mf[BATCH * CC * HW];
__device__ float g_gd[BATCH * CC * HW];
__device__ __align__(16) __half g_qh[BATCH * CC * HW];
__device__ __align__(16) __half g_kh[BATCH * CC * HW];
__device__ __align__(16) __half g_vh[BATCH * CC * HW];

// ---------------- helpers ----------------
typedef unsigned long long ull;
__device__ __forceinline__ ull pk2(float a, float b) {
    ull r; asm("mov.b64 %0, {%1, %2};" : "=l"(r) : "f"(a), "f"(b)); return r;
}
__device__ __forceinline__ void upk2(ull v, float& a, float& b) {
    asm("mov.b64 {%0, %1}, %2;" : "=f"(a), "=f"(b) : "l"(v));
}
__device__ __forceinline__ ull fma2(ull a, ull b, ull c) {
    ull d; asm("fma.rn.f32x2 %0, %1, %2, %3;" : "=l"(d) : "l"(a), "l"(b), "l"(c)); return d;
}
__device__ __forceinline__ uint32_t smem_u32(const void* p) {
    uint32_t a;
    asm("{ .reg .u64 t; cvta.to.shared.u64 t, %1; cvt.u32.u64 %0, t; }" : "=r"(a) : "l"(p));
    return a;
}
__device__ __forceinline__ float ex2f(float x) {
    float r; asm("ex2.approx.f32 %0, %1;" : "=f"(r) : "f"(x)); return r;
}
__device__ __forceinline__ uint32_t cvt_f16x2(float hi, float lo) {
    uint32_t r; asm("cvt.rn.f16x2.f32 %0, %1, %2;" : "=r"(r) : "f"(hi), "f"(lo)); return r;
}
__device__ __forceinline__ uint32_t ex2_h2(uint32_t a) {
    uint32_t r; asm("ex2.approx.f16x2 %0, %1;" : "=r"(r) : "r"(a)); return r;
}
__device__ __forceinline__ uint32_t hmax2(uint32_t a, uint32_t b) {
    uint32_t r; asm("max.f16x2 %0, %1, %2;" : "=r"(r) : "r"(a), "r"(b)); return r;
}
__device__ __forceinline__ uint32_t hadd2(uint32_t a, uint32_t b) {
    uint32_t r; asm("add.f16x2 %0, %1, %2;" : "=r"(r) : "r"(a), "r"(b)); return r;
}
__device__ __forceinline__ void ldsm4(uint32_t* r, uint32_t addr) {
    asm volatile("ldmatrix.sync.aligned.m8n8.x4.shared.b16 {%0,%1,%2,%3}, [%4];"
        : "=r"(r[0]), "=r"(r[1]), "=r"(r[2]), "=r"(r[3]) : "r"(addr));
}
__device__ __forceinline__ void ldsm4t(uint32_t* r, uint32_t addr) {
    asm volatile("ldmatrix.sync.aligned.m8n8.x4.trans.shared.b16 {%0,%1,%2,%3}, [%4];"
        : "=r"(r[0]), "=r"(r[1]), "=r"(r[2]), "=r"(r[3]) : "r"(addr));
}
__device__ __forceinline__ void mma16816(float* c, const uint32_t* a, const uint32_t* b) {
    asm volatile("mma.sync.aligned.m16n8k16.row.col.f32.f16.f16.f32 "
        "{%0,%1,%2,%3}, {%4,%5,%6,%7}, {%8,%9}, {%0,%1,%2,%3};"
        : "+f"(c[0]), "+f"(c[1]), "+f"(c[2]), "+f"(c[3])
        : "r"(a[0]), "r"(a[1]), "r"(a[2]), "r"(a[3]), "r"(b[0]), "r"(b[1]));
}
__device__ __forceinline__ void cp16(uint32_t saddr, const void* g) {
    asm volatile("cp.async.cg.shared.global [%0], [%1], 16;" :: "r"(saddr), "l"(g));
}
#define CP_COMMIT() asm volatile("cp.async.commit_group;" ::: "memory")
#define CP_WAIT1()  asm volatile("cp.async.wait_group 1;" ::: "memory")
#define CP_WAIT2()  asm volatile("cp.async.wait_group 2;" ::: "memory")

// ================================================================
// flash attention: fp16 QK/PV, Q fp16 prescaled, lazy-max softmax
// (threshold-8 trigger, packed-fp16 max tree). l via packed HADD2
// partial sums (no tensor work). Cross-tile pipeline, 4-stage ring.
// grid (32, HEADS, BATCH), 256 threads (8 warps), warp = 16 queries.
// ================================================================
#define STAGE 17408
#define NSTAGE 4
#define SB_Q (NSTAGE * STAGE)                 // 69632
#define SBUF_BYTES (SB_Q + 8704)              // 78336

__global__ void __launch_bounds__(256, 2) attn_mma() {
    extern __shared__ __align__(16) char sbuf[];
    const int tid = threadIdx.x;
    const int lane = tid & 31;
    const int w = tid >> 5;
    const int h = blockIdx.y, b = blockIdx.z;
    const int qb = blockIdx.x * 128;
    const size_t cbase = ((size_t)b * CC + h * 32) * HW;
    const __half* qgp = g_qh + cbase;
    const __half* kgp = g_kh + cbase;
    const __half* vgp = g_vh + cbase;
    const uint32_t sb = smem_u32(sbuf);

    // ---- cp.async prologue: Q (g0), stage0 (g1), stage1 (g2) ----
    const int cd = tid >> 3;
    const int cjh = (tid & 7) * 16;
    const uint32_t offK = (uint32_t)(cd * 136 + cjh) * 2;
    const uint32_t offV = 8704u + offK;
    const __half* gQ = qgp + (size_t)cd * HW + qb + cjh;
    const __half* gK = kgp + (size_t)cd * HW + cjh;
    const __half* gV = vgp + (size_t)cd * HW + cjh;
    cp16(sb + SB_Q + offK, gQ); cp16(sb + SB_Q + offK + 16, gQ + 8);
    CP_COMMIT();
    cp16(sb + offK, gK);       cp16(sb + offK + 16, gK + 8);
    cp16(sb + offV, gV);       cp16(sb + offV + 16, gV + 8);
    CP_COMMIT();
    cp16(sb + STAGE + offK, gK + 128); cp16(sb + STAGE + offK + 16, gK + 136);
    cp16(sb + STAGE + offV, gV + 128); cp16(sb + STAGE + offV + 16, gV + 136);
    CP_COMMIT();

    const int brow = (lane & 7) + ((lane & 16) >> 1);
    const int bcol8 = (lane & 8) ? 8 : 0;

    // ---- Q A-fragments ----
    CP_WAIT2();
    __syncthreads();
    uint32_t qa[2][4];
#pragma unroll
    for (int ks = 0; ks < 2; ks++)
        ldsm4t(qa[ks], sb + SB_Q + ((ks * 16 + brow) * 136 + w * 16 + bcol8) * 2);

    float mrow0 = 0.0f, mrow1 = 0.0f;
    float lr0 = 0.0f, lr1 = 0.0f;     // per-lane fp32 partial l
    float o[4][4];
#pragma unroll
    for (int nt = 0; nt < 4; nt++)
#pragma unroll
        for (int i = 0; i < 4; i++) o[nt][i] = 0.0f;

    float s[8][4];
    uint32_t pu[8][2];

    auto s_init = [&]() {
        float ns0 = -mrow0, ns1 = -mrow1;
#pragma unroll
        for (int nt = 0; nt < 8; nt++) {
            s[nt][0] = ns0; s[nt][1] = ns0;
            s[nt][2] = ns1; s[nt][3] = ns1;
        }
    };
    auto qk_piece = [&](uint32_t base, int idx, int joff) {
        int ks = idx >> 2, n0 = idx & 3;
        uint32_t bh[4];
        ldsm4t(bh, base + ((ks * 16 + (lane & 15)) * 136 +
                           joff + n0 * 16 + (lane >> 4) * 8) * 2);
        mma16816(s[n0 * 2], qa[ks], bh);
        mma16816(s[n0 * 2 + 1], qa[ks], bh + 2);
    };
    auto pv_piece = [&](uint32_t base, int ks, int joff) {
        uint32_t ah[4] = { pu[2 * ks][0], pu[2 * ks][1],
                           pu[2 * ks + 1][0], pu[2 * ks + 1][1] };
#pragma unroll
        for (int n0 = 0; n0 < 2; n0++) {
            uint32_t vh[4];
            ldsm4(vh, base + 8704 + ((n0 * 16 + brow) * 136 +
                                     joff + ks * 16 + bcol8) * 2);
            mma16816(o[n0 * 2], ah, vh);
            mma16816(o[n0 * 2 + 1], ah, vh + 2);
        }
    };
    auto softmax = [&]() {
        // cvt-first; packed fp16 max tree (overflow -> inf -> branch fires)
        uint32_t pc[8][2];
#pragma unroll
        for (int nt = 0; nt < 8; nt++) {
            pc[nt][0] = cvt_f16x2(s[nt][1], s[nt][0]);
            pc[nt][1] = cvt_f16x2(s[nt][3], s[nt][2]);
        }
        uint32_t ma = hmax2(hmax2(hmax2(pc[0][0], pc[1][0]), hmax2(pc[2][0], pc[3][0])),
                            hmax2(hmax2(pc[4][0], pc[5][0]), hmax2(pc[6][0], pc[7][0])));
        uint32_t mb = hmax2(hmax2(hmax2(pc[0][1], pc[1][1]), hmax2(pc[2][1], pc[3][1])),
                            hmax2(hmax2(pc[4][1], pc[5][1]), hmax2(pc[6][1], pc[7][1])));
        uint32_t mc = hmax2(ma, mb);
        __half2 mv = *(__half2*)&mc;
        float lm = fmaxf(__low2float(mv), __high2float(mv));
        if (__any_sync(0xffffffffu, lm > 8.0f)) {
            float mt0 = s[0][0], mt1 = s[0][2];
#pragma unroll
            for (int nt = 0; nt < 8; nt++) {
                mt0 = fmaxf(mt0, fmaxf(s[nt][0], s[nt][1]));
                mt1 = fmaxf(mt1, fmaxf(s[nt][2], s[nt][3]));
            }
            mt0 = fmaxf(mt0, __shfl_xor_sync(0xffffffffu, mt0, 1));
            mt0 = fmaxf(mt0, __shfl_xor_sync(0xffffffffu, mt0, 2));
            mt1 = fmaxf(mt1, __shfl_xor_sync(0xffffffffu, mt1, 1));
            mt1 = fmaxf(mt1, __shfl_xor_sync(0xffffffffu, mt1, 2));
            float d0 = fmaxf(mt0, 0.0f), d1 = fmaxf(mt1, 0.0f);
            float c0 = ex2f(-d0), c1 = ex2f(-d1);
            mrow0 += d0; mrow1 += d1;
#pragma unroll
            for (int nt = 0; nt < 4; nt++) {
                o[nt][0] *= c0; o[nt][1] *= c0;
                o[nt][2] *= c1; o[nt][3] *= c1;
            }
            lr0 *= c0; lr1 *= c1;
#pragma unroll
            for (int nt = 0; nt < 8; nt++) {
                s[nt][0] -= d0; s[nt][1] -= d0;
                s[nt][2] -= d1; s[nt][3] -= d1;
                pc[nt][0] = cvt_f16x2(s[nt][1], s[nt][0]);
                pc[nt][1] = cvt_f16x2(s[nt][3], s[nt][2]);
            }
        }
#pragma unroll
        for (int nt = 0; nt < 8; nt++) {
            pu[nt][0] = ex2_h2(pc[nt][0]);
            pu[nt][1] = ex2_h2(pc[nt][1]);
        }
        // l partials via packed HADD2 trees (sums <= 4096 << fp16 max)
        uint32_t sa = hadd2(hadd2(hadd2(pu[0][0], pu[1][0]), hadd2(pu[2][0], pu[3][0])),
                            hadd2(hadd2(pu[4][0], pu[5][0]), hadd2(pu[6][0], pu[7][0])));
        uint32_t sbm = hadd2(hadd2(hadd2(pu[0][1], pu[1][1]), hadd2(pu[2][1], pu[3][1])),
                             hadd2(hadd2(pu[4][1], pu[5][1]), hadd2(pu[6][1], pu[7][1])));
        __half2 va = *(__half2*)&sa;
        __half2 vb = *(__half2*)&sbm;
        lr0 += __low2float(va) + __high2float(va);
        lr1 += __low2float(vb) + __high2float(vb);
    };

    // ---- ensure stage0 visible, then issue QK(h0, tile0) ----
    CP_WAIT1();
    __syncthreads();
    s_init();
#pragma unroll
    for (int i = 0; i < 8; i++) qk_piece(sb, i, 0);

#pragma unroll 4
    for (int t = 0; t < 32; t++) {
        const uint32_t bcur = sb + (uint32_t)(t & 3) * STAGE;
        const uint32_t bnxt = sb + (uint32_t)((t + 1) & 3) * STAGE;

        softmax();            // h0 -> pu
        s_init();             // s for h1
#pragma unroll
        for (int ks = 0; ks < 4; ks++) {
            pv_piece(bcur, ks, 0);
            qk_piece(bcur, 2 * ks, 64);
            qk_piece(bcur, 2 * ks + 1, 64);
        }
        softmax();            // h1 -> pu

        if (t + 2 < 32) {
            const uint32_t so = sb + (uint32_t)((t + 2) & 3) * STAGE;
            const int go = (t + 2) * 128;
            cp16(so + offK, gK + go);       cp16(so + offK + 16, gK + go + 8);
            cp16(so + offV, gV + go);       cp16(so + offV + 16, gV + go + 8);
        }
        CP_COMMIT();
        CP_WAIT1();
        __syncthreads();

        if (t < 31) {
            s_init();
#pragma unroll
            for (int ks = 0; ks < 4; ks++) {
                pv_piece(bcur, ks, 64);
                qk_piece(bnxt, 2 * ks, 0);
                qk_piece(bnxt, 2 * ks + 1, 0);
            }
        } else {
#pragma unroll
            for (int ks = 0; ks < 4; ks++) pv_piece(bcur, ks, 64);
        }
    }

    // ---------------- finalize (quad-reduce l once) ----------------
    lr0 += __shfl_xor_sync(0xffffffffu, lr0, 1);
    lr0 += __shfl_xor_sync(0xffffffffu, lr0, 2);
    lr1 += __shfl_xor_sync(0xffffffffu, lr1, 1);
    lr1 += __shfl_xor_sync(0xffffffffu, lr1, 2);
    float i0 = 1.0f / lr0, i1 = 1.0f / lr1;
    int pix = qb + w * 16 + (lane >> 2);
#pragma unroll
    for (int nt = 0; nt < 4; nt++) {
        int d = nt * 8 + 2 * (lane & 3);
        g_gd[cbase + (size_t)d * HW + pix] = o[nt][0] * i0;
        g_gd[cbase + (size_t)(d + 1) * HW + pix] = o[nt][1] * i0;
        g_gd[cbase + (size_t)d * HW + pix + 8] = o[nt][2] * i1;
        g_gd[cbase + (size_t)(d + 1) * HW + pix + 8] = o[nt][3] * i1;
    }
}

// ================================================================
// input 1x1 conv via HMMA -> fp16 outputs (unchanged).
// ================================================================
template<bool DUAL>
__global__ __launch_bounds__(256) void conv_in(
    const float* __restrict__ X,
    const float* __restrict__ W1, const float* __restrict__ b1,
    __half* __restrict__ H1, float hscale,
    const float* __restrict__ W2, const float* __restrict__ b2,
    __half* __restrict__ H2) {
    extern __shared__ __align__(16) char dsm[];
    const int tid = threadIdx.x;
    const int lane = tid & 31;
    const int w = tid >> 5;
    const int bb = blockIdx.y;
    const int p0 = blockIdx.x * 32;
    const uint32_t sb = smem_u32(dsm);
    const int brow = (lane & 7) + ((lane & 16) >> 1);
    const int bcol8 = (lane & 8) ? 8 : 0;

    float4 xreg[4];
#pragma unroll
    for (int i = 0; i < 4; i++) {
        int idx = i * 256 + tid;
        int ci = idx >> 3, px = (idx & 7) * 4;
        xreg[i] = *(const float4*)(X + ((size_t)bb * CC + ci) * HW + p0 + px);
    }

#pragma unroll
    for (int i = 0; i < 16; i++) {
        int idx = i * 256 + tid;
        int co = idx >> 5, ci = (idx & 31) * 4;
        float4 v = *(const float4*)(W1 + co * CC + ci);
        __half* d = (__half*)(dsm) + co * 136 + ci;
        d[0] = __float2half(v.x); d[1] = __float2half(v.y);
        d[2] = __float2half(v.z); d[3] = __float2half(v.w);
    }
    if (DUAL) {
#pragma unroll
        for (int i = 0; i < 16; i++) {
            int idx = i * 256 + tid;
            int co = idx >> 5, ci = (idx & 31) * 4;
            float4 v = *(const float4*)(W2 + co * CC + ci);
            __half* d = (__half*)(dsm + 34816) + co * 136 + ci;
            d[0] = __float2half(v.x); d[1] = __float2half(v.y);
            d[2] = __float2half(v.z); d[3] = __float2half(v.w);
        }
    }
    __syncthreads();
    uint32_t wa1[8][4], wa2[8][4];
    {
        int row = w * 16 + (lane & 15);
        int colb = (lane >> 4) * 8;
#pragma unroll
        for (int ks = 0; ks < 8; ks++) {
            ldsm4(wa1[ks], sb + (row * 136 + ks * 16 + colb) * 2);
            if (DUAL)
                ldsm4(wa2[ks], sb + 34816 + (row * 136 + ks * 16 + colb) * 2);
        }
    }
    __syncthreads();

#pragma unroll
    for (int i = 0; i < 4; i++) {
        int idx = i * 256 + tid;
        int ci = idx >> 3, px = (idx & 7) * 4;
        float vv[4] = { xreg[i].x, xreg[i].y, xreg[i].z, xreg[i].w };
#pragma unroll
        for (int j = 0; j < 4; j++)
            *((__half*)(dsm) + (px + j) * 136 + ci) = __float2half(vv[j]);
    }
    __syncthreads();

    float acc1[4][4], acc2[4][4];
#pragma unroll
    for (int nt = 0; nt < 4; nt++)
#pragma unroll
        for (int i = 0; i < 4; i++) { acc1[nt][i] = 0.0f; acc2[nt][i] = 0.0f; }

#pragma unroll
    for (int ks = 0; ks < 8; ks++) {
#pragma unroll
        for (int n0 = 0; n0 < 2; n0++) {
            uint32_t bh[4];
            ldsm4(bh, sb + ((n0 * 16 + brow) * 136 + ks * 16 + bcol8) * 2);
            mma16816(acc1[n0 * 2], wa1[ks], bh);
            mma16816(acc1[n0 * 2 + 1], wa1[ks], bh + 2);
            if (DUAL) {
                mma16816(acc2[n0 * 2], wa2[ks], bh);
                mma16816(acc2[n0 * 2 + 1], wa2[ks], bh + 2);
            }
        }
    }

    int coA = w * 16 + (lane >> 2);
    int coB = coA + 8;
    float b1A = b1[coA], b1B = b1[coB];
    float b2A = 0.0f, b2B = 0.0f;
    if (DUAL) { b2A = b2[coA]; b2B = b2[coB]; }
    size_t baseA = ((size_t)bb * CC + coA) * HW + p0;
    size_t baseB = ((size_t)bb * CC + coB) * HW + p0;
#pragma unroll
    for (int nt = 0; nt < 4; nt++) {
        int px = nt * 8 + 2 * (lane & 3);
        *(uint32_t*)(H1 + baseA + px) =
            cvt_f16x2((acc1[nt][1] + b1A) * hscale, (acc1[nt][0] + b1A) * hscale);
        *(uint32_t*)(H1 + baseB + px) =
            cvt_f16x2((acc1[nt][3] + b1B) * hscale, (acc1[nt][2] + b1B) * hscale);
        if (DUAL) {
            *(uint32_t*)(H2 + baseA + px) =
                cvt_f16x2(acc2[nt][1] + b2A, acc2[nt][0] + b2A);
            *(uint32_t*)(H2 + baseB + px) =
                cvt_f16x2(acc2[nt][3] + b2B, acc2[nt][2] + b2B);
        }
    }
}

// ================================================================
// output conv: hi-only fp16 X (precision budget allows) + residual.
// ================================================================
__global__ __launch_bounds__(256) void conv_out(
    const float* __restrict__ X,
    const float* __restrict__ W1, const float* __restrict__ b1,
    float* __restrict__ Y1, const float* __restrict__ resid) {
    __shared__ __align__(16) char sbufc[34816];
    const int tid = threadIdx.x;
    const int lane = tid & 31;
    const int w = tid >> 5;
    const int bb = blockIdx.y;
    const int p0 = blockIdx.x * 32;
    const uint32_t sb = smem_u32(sbufc);
    const int brow = (lane & 7) + ((lane & 16) >> 1);
    const int bcol8 = (lane & 8) ? 8 : 0;

    float4 xreg[4];
#pragma unroll
    for (int i = 0; i < 4; i++) {
        int idx = i * 256 + tid;
        int ci = idx >> 3, px = (idx & 7) * 4;
        xreg[i] = *(const float4*)(X + ((size_t)bb * CC + ci) * HW + p0 + px);
    }

    uint32_t wa1[8][4];
    {
#pragma unroll
        for (int i = 0; i < 16; i++) {
            int idx = i * 256 + tid;
            int co = idx >> 5, ci = (idx & 31) * 4;
            float4 v = *(const float4*)(W1 + co * CC + ci);
            __half* d = (__half*)(sbufc) + co * 136 + ci;
            d[0] = __float2half(v.x); d[1] = __float2half(v.y);
            d[2] = __float2half(v.z); d[3] = __float2half(v.w);
        }
        __syncthreads();
        int row = w * 16 + (lane & 15);
        int colb = (lane >> 4) * 8;
#pragma unroll
        for (int ks = 0; ks < 8; ks++)
            ldsm4(wa1[ks], sb + (row * 136 + ks * 16 + colb) * 2);
        __syncthreads();
    }

#pragma unroll
    for (int i = 0; i < 4; i++) {
        int idx = i * 256 + tid;
        int ci = idx >> 3, px = (idx & 7) * 4;
        float vv[4] = { xreg[i].x, xreg[i].y, xreg[i].z, xreg[i].w };
#pragma unroll
        for (int j = 0; j < 4; j++)
            *((__half*)(sbufc) + (px + j) * 136 + ci) = __float2half(vv[j]);
    }
    __syncthreads();

    float acc1[4][4];
#pragma unroll
    for (int nt = 0; nt < 4; nt++)
#pragma unroll
        for (int i = 0; i < 4; i++) acc1[nt][i] = 0.0f;

#pragma unroll
    for (int ks = 0; ks < 8; ks++) {
#pragma unroll
        for (int n0 = 0; n0 < 2; n0++) {
            uint32_t bh[4];
            ldsm4(bh, sb + ((n0 * 16 + brow) * 136 + ks * 16 + bcol8) * 2);
            mma16816(acc1[n0 * 2], wa1[ks], bh);
            mma16816(acc1[n0 * 2 + 1], wa1[ks], bh + 2);
        }
    }

    int coA = w * 16 + (lane >> 2);
    int coB = coA + 8;
    float b1A = b1[coA], b1B = b1[coB];
    size_t baseA = ((size_t)bb * CC + coA) * HW + p0;
    size_t baseB = ((size_t)bb * CC + coB) * HW + p0;
#pragma unroll
    for (int nt = 0; nt < 4; nt++) {
        int px = nt * 8 + 2 * (lane & 3);
        float2 rA = *(const float2*)(resid + baseA + px);
        float2 rB = *(const float2*)(resid + baseB + px);
        *(float2*)(Y1 + baseA + px) =
            make_float2(acc1[nt][0] + b1A + rA.x, acc1[nt][1] + b1A + rA.y);
        *(float2*)(Y1 + baseB + px) =
            make_float2(acc1[nt][2] + b1B + rB.x, acc1[nt][3] + b1B + rB.y);
    }
}

// ================= fused mask convs, conv2 on packed FMA2 (unchanged) ========
__global__ __launch_bounds__(256) void mask_fused(const float* __restrict__ seg,
                                                  const float* __restrict__ Wm1,
                                                  const float* __restrict__ bm1,
                                                  const float* __restrict__ Wm2,
                                                  const float* __restrict__ bm2) {
    int y = blockIdx.x, b = blockIdx.y;
    __shared__ float sseg[5][66];
    __shared__ __align__(8) float2 smi[3][66][16];
    const float* sgb = seg + (size_t)b * HW;
    for (int i = threadIdx.x; i < 5 * 66; i += 256) {
        int r = i / 66, x = i % 66;
        int yy = y + r - 2, xx = x - 1;
        sseg[r][x] = (yy >= 0 && yy < 64 && xx >= 0 && xx < 64)
                     ? sgb[yy * 64 + xx] : 0.0f;
    }
    __syncthreads();
    for (int i = threadIdx.x; i < 32 * 3 * 66; i += 256) {
        int c = i / 198, rem = i % 198, r = rem / 66, x = rem % 66;
        int yy = y + r - 1, xx = x - 1;
        float v = 0.0f;
        if (yy >= 0 && yy < 64 && xx >= 0 && xx < 64) {
            float acc = bm1[c];
            const float* wp = Wm1 + c * 9;
#pragma unroll
            for (int dy = 0; dy < 3; dy++)
#pragma unroll
                for (int dx = 0; dx < 3; dx++)
                    acc += wp[dy * 3 + dx] * sseg[r + dy][x + dx - 1];
            v = fmaxf(acc, 0.0f);
        }
        ((float*)&smi[r][x][c >> 1])[c & 1] = v;
    }
    __syncthreads();

    int co = threadIdx.x >> 1;
    int xh = (threadIdx.x & 1) * 32;
    ull acc2[32];
    float bb = bm2[co];
#pragma unroll
    for (int p = 0; p < 32; p++) acc2[p] = pk2(bb, 0.0f);
    const float* wbase = Wm2 + co * 288;

    for (int c2 = 0; c2 < 16; c2++) {
#pragma unroll
        for (int r = 0; r < 3; r++) {
            ull rv[34];
#pragma unroll
            for (int t = 0; t < 34; t++)
                rv[t] = *(const ull*)&smi[r][xh + t][c2];
            const float* wp = wbase + (2 * c2) * 9 + r * 3;
            const float* wq = wp + 9;
#pragma unroll
            for (int dx = 0; dx < 3; dx++) {
                ull w2 = pk2(wp[dx], wq[dx]);
#pragma unroll
                for (int p = 0; p < 32; p++)
                    acc2[p] = fma2(w2, rv[p + dx], acc2[p]);
            }
        }
    }

    float* out = g_mf + ((size_t)b * CC + co) * HW + y * 64 + xh;
#pragma unroll
    for (int p = 0; p < 32; p++) {
        float lo, hi;
        upk2(acc2[p], lo, hi);
        out[p] = lo + hi;
    }
}

// ---------------- launch ----------------
extern "C" void kernel_launch(void* const* d_in, const int* in_sizes, int n_in,
                              void* d_out, int out_size) {
    const float* sr  = (const float*)d_in[0];
    const float* seg = (const float*)d_in[1];
    const float* Wq  = (const float*)d_in[2];
    const float* bq  = (const float*)d_in[3];
    const float* Wm1 = (const float*)d_in[4];
    const float* bm1 = (const float*)d_in[5];
    const float* Wm2 = (const float*)d_in[6];
    const float* bm2 = (const float*)d_in[7];
    const float* Wk  = (const float*)d_in[8];
    const float* bk  = (const float*)d_in[9];
    const float* Wv  = (const float*)d_in[10];
    const float* bv  = (const float*)d_in[11];
    const float* Wo  = (const float*)d_in[12];
    const float* bo  = (const float*)d_in[13];
    float* out = (float*)d_out;

    float *pmf, *pg;
    __half *pqh, *pkh, *pvh;
    cudaGetSymbolAddress((void**)&pmf, g_mf);
    cudaGetSymbolAddress((void**)&pg, g_gd);
    cudaGetSymbolAddress((void**)&pqh, g_qh);
    cudaGetSymbolAddress((void**)&pkh, g_kh);
    cudaGetSymbolAddress((void**)&pvh, g_vh);

    static cudaStream_t s2 = nullptr;
    static cudaEvent_t e0 = nullptr, e1 = nullptr;
    if (s2 == nullptr) {
        cudaStreamCreateWithFlags(&s2, cudaStreamNonBlocking);
        cudaEventCreateWithFlags(&e0, cudaEventDisableTiming);
        cudaEventCreateWithFlags(&e1, cudaEventDisableTiming);
    }

    cudaFuncSetAttribute(attn_mma, cudaFuncAttributeMaxDynamicSharedMemorySize,
                         SBUF_BYTES);
    cudaFuncSetAttribute(conv_in<true>,
                         cudaFuncAttributeMaxDynamicSharedMemorySize, 69632);

    cudaEventRecord(e0, 0);
    cudaStreamWaitEvent(s2, e0, 0);
    conv_in<false><<<dim3(HW / 32, BATCH), 256, 34816, s2>>>(
        sr, Wq, bq, pqh, SCALE2, nullptr, nullptr, nullptr);
    cudaEventRecord(e1, s2);

    mask_fused<<<dim3(64, BATCH), 256>>>(seg, Wm1, bm1, Wm2, bm2);
    conv_in<true><<<dim3(HW / 32, BATCH), 256, 69632>>>(
        pmf, Wk, bk, pkh, 1.0f, Wv, bv, pvh);

    cudaStreamWaitEvent(0, e1, 0);
    attn_mma<<<dim3(32, HEADS, BATCH), 256, SBUF_BYTES>>>();
    conv_out<<<dim3(HW / 32, BATCH), 256>>>(pg, Wo, bo, out, sr);
}

// round 15
// speedup vs baseline: 1.0168x; 1.0168x over previous
#include <cuda_runtime.h>
#include <cuda_fp16.h>
#include <cstdint>
#include <cstddef>

#define BATCH 2
#define CC 128
#define HW 4096
#define HEADS 4
// 32^-0.5 * log2(e): softmax in base-2
#define SCALE2 0.25500526764086436f

// ---------------- scratch ----------------
__device__ float g_mf[BATCH * CC * HW];
__device__ float g_gd[BATCH * CC * HW];
__device__ __align__(16) __half g_qh[BATCH * CC * HW];
__device__ __align__(16) __half g_kh[BATCH * CC * HW];
__device__ __align__(16) __half g_vh[BATCH * CC * HW];

// ---------------- helpers ----------------
typedef unsigned long long ull;
__device__ __forceinline__ ull pk2(float a, float b) {
    ull r; asm("mov.b64 %0, {%1, %2};" : "=l"(r) : "f"(a), "f"(b)); return r;
}
__device__ __forceinline__ void upk2(ull v, float& a, float& b) {
    asm("mov.b64 {%0, %1}, %2;" : "=f"(a), "=f"(b) : "l"(v));
}
__device__ __forceinline__ ull fma2(ull a, ull b, ull c) {
    ull d; asm("fma.rn.f32x2 %0, %1, %2, %3;" : "=l"(d) : "l"(a), "l"(b), "l"(c)); return d;
}
__device__ __forceinline__ uint32_t smem_u32(const void* p) {
    uint32_t a;
    asm("{ .reg .u64 t; cvta.to.shared.u64 t, %1; cvt.u32.u64 %0, t; }" : "=r"(a) : "l"(p));
    return a;
}
__device__ __forceinline__ float ex2f(float x) {
    float r; asm("ex2.approx.f32 %0, %1;" : "=f"(r) : "f"(x)); return r;
}
__device__ __forceinline__ uint32_t cvt_f16x2(float hi, float lo) {
    uint32_t r; asm("cvt.rn.f16x2.f32 %0, %1, %2;" : "=r"(r) : "f"(hi), "f"(lo)); return r;
}
__device__ __forceinline__ uint32_t ex2_h2(uint32_t a) {
    uint32_t r; asm("ex2.approx.f16x2 %0, %1;" : "=r"(r) : "r"(a)); return r;
}
__device__ __forceinline__ void ldsm4(uint32_t* r, uint32_t addr) {
    asm volatile("ldmatrix.sync.aligned.m8n8.x4.shared.b16 {%0,%1,%2,%3}, [%4];"
        : "=r"(r[0]), "=r"(r[1]), "=r"(r[2]), "=r"(r[3]) : "r"(addr));
}
__device__ __forceinline__ void ldsm4t(uint32_t* r, uint32_t addr) {
    asm volatile("ldmatrix.sync.aligned.m8n8.x4.trans.shared.b16 {%0,%1,%2,%3}, [%4];"
        : "=r"(r[0]), "=r"(r[1]), "=r"(r[2]), "=r"(r[3]) : "r"(addr));
}
__device__ __forceinline__ void mma16816(float* c, const uint32_t* a, const uint32_t* b) {
    asm volatile("mma.sync.aligned.m16n8k16.row.col.f32.f16.f16.f32 "
        "{%0,%1,%2,%3}, {%4,%5,%6,%7}, {%8,%9}, {%0,%1,%2,%3};"
        : "+f"(c[0]), "+f"(c[1]), "+f"(c[2]), "+f"(c[3])
        : "r"(a[0]), "r"(a[1]), "r"(a[2]), "r"(a[3]), "r"(b[0]), "r"(b[1]));
}
__device__ __forceinline__ void cp16(uint32_t saddr, const void* g) {
    asm volatile("cp.async.cg.shared.global [%0], [%1], 16;" :: "r"(saddr), "l"(g));
}
#define CP_COMMIT() asm volatile("cp.async.commit_group;" ::: "memory")
#define CP_WAIT1()  asm volatile("cp.async.wait_group 1;" ::: "memory")
#define CP_WAIT2()  asm volatile("cp.async.wait_group 2;" ::: "memory")

// ================================================================
// flash attention (R13 version): fp16 QK/PV, Q fp16 prescaled,
// lazy-max softmax (threshold-8), l via constant ones-column MMA,
// cross-tile pipeline, 4-stage cp.async ring with unroll-4.
// grid (32, HEADS, BATCH), 256 threads (8 warps), warp = 16 queries.
// ================================================================
#define STAGE 17408
#define NSTAGE 4
#define SB_Q (NSTAGE * STAGE)                 // 69632
#define SBUF_BYTES (SB_Q + 8704)              // 78336

__global__ void __launch_bounds__(256, 2) attn_mma() {
    extern __shared__ __align__(16) char sbuf[];
    const int tid = threadIdx.x;
    const int lane = tid & 31;
    const int w = tid >> 5;
    const int h = blockIdx.y, b = blockIdx.z;
    const int qb = blockIdx.x * 128;
    const size_t cbase = ((size_t)b * CC + h * 32) * HW;
    const __half* qgp = g_qh + cbase;
    const __half* kgp = g_kh + cbase;
    const __half* vgp = g_vh + cbase;
    const uint32_t sb = smem_u32(sbuf);

    // ---- cp.async prologue: Q (g0), stage0 (g1), stage1 (g2) ----
    const int cd = tid >> 3;
    const int cjh = (tid & 7) * 16;
    const uint32_t offK = (uint32_t)(cd * 136 + cjh) * 2;
    const uint32_t offV = 8704u + offK;
    const __half* gQ = qgp + (size_t)cd * HW + qb + cjh;
    const __half* gK = kgp + (size_t)cd * HW + cjh;
    const __half* gV = vgp + (size_t)cd * HW + cjh;
    cp16(sb + SB_Q + offK, gQ); cp16(sb + SB_Q + offK + 16, gQ + 8);
    CP_COMMIT();
    cp16(sb + offK, gK);       cp16(sb + offK + 16, gK + 8);
    cp16(sb + offV, gV);       cp16(sb + offV + 16, gV + 8);
    CP_COMMIT();
    cp16(sb + STAGE + offK, gK + 128); cp16(sb + STAGE + offK + 16, gK + 136);
    cp16(sb + STAGE + offV, gV + 128); cp16(sb + STAGE + offV + 16, gV + 136);
    CP_COMMIT();

    const int brow = (lane & 7) + ((lane & 16) >> 1);
    const int bcol8 = (lane & 8) ? 8 : 0;

    // ---- Q A-fragments ----
    CP_WAIT2();
    __syncthreads();
    uint32_t qa[2][4];
#pragma unroll
    for (int ks = 0; ks < 2; ks++)
        ldsm4t(qa[ks], sb + SB_Q + ((ks * 16 + brow) * 136 + w * 16 + bcol8) * 2);

    const uint32_t b2c[2] = { (lane < 4) ? 0x3C003C00u : 0u,
                              (lane < 4) ? 0x3C003C00u : 0u };

    float mrow0 = 0.0f, mrow1 = 0.0f;
    float o[4][4], ol[4];
#pragma unroll
    for (int nt = 0; nt < 4; nt++)
#pragma unroll
        for (int i = 0; i < 4; i++) o[nt][i] = 0.0f;
#pragma unroll
    for (int i = 0; i < 4; i++) ol[i] = 0.0f;

    float s[8][4];
    uint32_t pu[8][2];

    auto s_init = [&]() {
        float ns0 = -mrow0, ns1 = -mrow1;
#pragma unroll
        for (int nt = 0; nt < 8; nt++) {
            s[nt][0] = ns0; s[nt][1] = ns0;
            s[nt][2] = ns1; s[nt][3] = ns1;
        }
    };
    auto qk_piece = [&](uint32_t base, int idx, int joff) {
        int ks = idx >> 2, n0 = idx & 3;
        uint32_t bh[4];
        ldsm4t(bh, base + ((ks * 16 + (lane & 15)) * 136 +
                           joff + n0 * 16 + (lane >> 4) * 8) * 2);
        mma16816(s[n0 * 2], qa[ks], bh);
        mma16816(s[n0 * 2 + 1], qa[ks], bh + 2);
    };
    auto pv_piece = [&](uint32_t base, int ks, int joff) {
        uint32_t ah[4] = { pu[2 * ks][0], pu[2 * ks][1],
                           pu[2 * ks + 1][0], pu[2 * ks + 1][1] };
#pragma unroll
        for (int n0 = 0; n0 < 2; n0++) {
            uint32_t vh[4];
            ldsm4(vh, base + 8704 + ((n0 * 16 + brow) * 136 +
                                     joff + ks * 16 + bcol8) * 2);
            mma16816(o[n0 * 2], ah, vh);
            mma16816(o[n0 * 2 + 1], ah, vh + 2);
        }
        mma16816(ol, ah, b2c);
    };
    auto softmax = [&]() {
        float mt0 = s[0][0], mt1 = s[0][2];
#pragma unroll
        for (int nt = 0; nt < 8; nt++) {
            mt0 = fmaxf(mt0, fmaxf(s[nt][0], s[nt][1]));
            mt1 = fmaxf(mt1, fmaxf(s[nt][2], s[nt][3]));
        }
        if (__any_sync(0xffffffffu, fmaxf(mt0, mt1) > 8.0f)) {
            mt0 = fmaxf(mt0, __shfl_xor_sync(0xffffffffu, mt0, 1));
            mt0 = fmaxf(mt0, __shfl_xor_sync(0xffffffffu, mt0, 2));
            mt1 = fmaxf(mt1, __shfl_xor_sync(0xffffffffu, mt1, 1));
            mt1 = fmaxf(mt1, __shfl_xor_sync(0xffffffffu, mt1, 2));
            float d0 = fmaxf(mt0, 0.0f), d1 = fmaxf(mt1, 0.0f);
            float c0 = ex2f(-d0), c1 = ex2f(-d1);
            mrow0 += d0; mrow1 += d1;
#pragma unroll
            for (int nt = 0; nt < 4; nt++) {
                o[nt][0] *= c0; o[nt][1] *= c0;
                o[nt][2] *= c1; o[nt][3] *= c1;
            }
            ol[0] *= c0; ol[1] *= c0; ol[2] *= c1; ol[3] *= c1;
#pragma unroll
            for (int nt = 0; nt < 8; nt++) {
                s[nt][0] -= d0; s[nt][1] -= d0;
                s[nt][2] -= d1; s[nt][3] -= d1;
            }
        }
#pragma unroll
        for (int nt = 0; nt < 8; nt++) {
            pu[nt][0] = ex2_h2(cvt_f16x2(s[nt][1], s[nt][0]));
            pu[nt][1] = ex2_h2(cvt_f16x2(s[nt][3], s[nt][2]));
        }
    };

    // ---- ensure stage0 visible, then issue QK(h0, tile0) ----
    CP_WAIT1();
    __syncthreads();
    s_init();
#pragma unroll
    for (int i = 0; i < 8; i++) qk_piece(sb, i, 0);

#pragma unroll 4
    for (int t = 0; t < 32; t++) {
        const uint32_t bcur = sb + (uint32_t)(t & 3) * STAGE;
        const uint32_t bnxt = sb + (uint32_t)((t + 1) & 3) * STAGE;

        softmax();            // h0 -> pu
        s_init();             // s for h1
#pragma unroll
        for (int ks = 0; ks < 4; ks++) {
            pv_piece(bcur, ks, 0);
            qk_piece(bcur, 2 * ks, 64);
            qk_piece(bcur, 2 * ks + 1, 64);
        }
        softmax();            // h1 -> pu

        if (t + 2 < 32) {
            const uint32_t so = sb + (uint32_t)((t + 2) & 3) * STAGE;
            const int go = (t + 2) * 128;
            cp16(so + offK, gK + go);       cp16(so + offK + 16, gK + go + 8);
            cp16(so + offV, gV + go);       cp16(so + offV + 16, gV + go + 8);
        }
        CP_COMMIT();
        CP_WAIT1();
        __syncthreads();

        if (t < 31) {
            s_init();
#pragma unroll
            for (int ks = 0; ks < 4; ks++) {
                pv_piece(bcur, ks, 64);
                qk_piece(bnxt, 2 * ks, 0);
                qk_piece(bnxt, 2 * ks + 1, 0);
            }
        } else {
#pragma unroll
            for (int ks = 0; ks < 4; ks++) pv_piece(bcur, ks, 64);
        }
    }

    // ---------------- finalize ----------------
    float l0 = __shfl_sync(0xffffffffu, ol[0], lane & 28);
    float l1 = __shfl_sync(0xffffffffu, ol[2], lane & 28);
    float i0 = 1.0f / l0, i1 = 1.0f / l1;
    int pix = qb + w * 16 + (lane >> 2);
#pragma unroll
    for (int nt = 0; nt < 4; nt++) {
        int d = nt * 8 + 2 * (lane & 3);
        g_gd[cbase + (size_t)d * HW + pix] = o[nt][0] * i0;
        g_gd[cbase + (size_t)(d + 1) * HW + pix] = o[nt][1] * i0;
        g_gd[cbase + (size_t)d * HW + pix + 8] = o[nt][2] * i1;
        g_gd[cbase + (size_t)(d + 1) * HW + pix + 8] = o[nt][3] * i1;
    }
}

// ================================================================
// input 1x1 conv via HMMA -> fp16 outputs (unchanged).
// ================================================================
template<bool DUAL>
__global__ __launch_bounds__(256) void conv_in(
    const float* __restrict__ X,
    const float* __restrict__ W1, const float* __restrict__ b1,
    __half* __restrict__ H1, float hscale,
    const float* __restrict__ W2, const float* __restrict__ b2,
    __half* __restrict__ H2) {
    extern __shared__ __align__(16) char dsm[];
    const int tid = threadIdx.x;
    const int lane = tid & 31;
    const int w = tid >> 5;
    const int bb = blockIdx.y;
    const int p0 = blockIdx.x * 32;
    const uint32_t sb = smem_u32(dsm);
    const int brow = (lane & 7) + ((lane & 16) >> 1);
    const int bcol8 = (lane & 8) ? 8 : 0;

    float4 xreg[4];
#pragma unroll
    for (int i = 0; i < 4; i++) {
        int idx = i * 256 + tid;
        int ci = idx >> 3, px = (idx & 7) * 4;
        xreg[i] = *(const float4*)(X + ((size_t)bb * CC + ci) * HW + p0 + px);
    }

#pragma unroll
    for (int i = 0; i < 16; i++) {
        int idx = i * 256 + tid;
        int co = idx >> 5, ci = (idx & 31) * 4;
        float4 v = *(const float4*)(W1 + co * CC + ci);
        __half* d = (__half*)(dsm) + co * 136 + ci;
        d[0] = __float2half(v.x); d[1] = __float2half(v.y);
        d[2] = __float2half(v.z); d[3] = __float2half(v.w);
    }
    if (DUAL) {
#pragma unroll
        for (int i = 0; i < 16; i++) {
            int idx = i * 256 + tid;
            int co = idx >> 5, ci = (idx & 31) * 4;
            float4 v = *(const float4*)(W2 + co * CC + ci);
            __half* d = (__half*)(dsm + 34816) + co * 136 + ci;
            d[0] = __float2half(v.x); d[1] = __float2half(v.y);
            d[2] = __float2half(v.z); d[3] = __float2half(v.w);
        }
    }
    __syncthreads();
    uint32_t wa1[8][4], wa2[8][4];
    {
        int row = w * 16 + (lane & 15);
        int colb = (lane >> 4) * 8;
#pragma unroll
        for (int ks = 0; ks < 8; ks++) {
            ldsm4(wa1[ks], sb + (row * 136 + ks * 16 + colb) * 2);
            if (DUAL)
                ldsm4(wa2[ks], sb + 34816 + (row * 136 + ks * 16 + colb) * 2);
        }
    }
    __syncthreads();

#pragma unroll
    for (int i = 0; i < 4; i++) {
        int idx = i * 256 + tid;
        int ci = idx >> 3, px = (idx & 7) * 4;
        float vv[4] = { xreg[i].x, xreg[i].y, xreg[i].z, xreg[i].w };
#pragma unroll
        for (int j = 0; j < 4; j++)
            *((__half*)(dsm) + (px + j) * 136 + ci) = __float2half(vv[j]);
    }
    __syncthreads();

    float acc1[4][4], acc2[4][4];
#pragma unroll
    for (int nt = 0; nt < 4; nt++)
#pragma unroll
        for (int i = 0; i < 4; i++) { acc1[nt][i] = 0.0f; acc2[nt][i] = 0.0f; }

#pragma unroll
    for (int ks = 0; ks < 8; ks++) {
#pragma unroll
        for (int n0 = 0; n0 < 2; n0++) {
            uint32_t bh[4];
            ldsm4(bh, sb + ((n0 * 16 + brow) * 136 + ks * 16 + bcol8) * 2);
            mma16816(acc1[n0 * 2], wa1[ks], bh);
            mma16816(acc1[n0 * 2 + 1], wa1[ks], bh + 2);
            if (DUAL) {
                mma16816(acc2[n0 * 2], wa2[ks], bh);
                mma16816(acc2[n0 * 2 + 1], wa2[ks], bh + 2);
            }
        }
    }

    int coA = w * 16 + (lane >> 2);
    int coB = coA + 8;
    float b1A = b1[coA], b1B = b1[coB];
    float b2A = 0.0f, b2B = 0.0f;
    if (DUAL) { b2A = b2[coA]; b2B = b2[coB]; }
    size_t baseA = ((size_t)bb * CC + coA) * HW + p0;
    size_t baseB = ((size_t)bb * CC + coB) * HW + p0;
#pragma unroll
    for (int nt = 0; nt < 4; nt++) {
        int px = nt * 8 + 2 * (lane & 3);
        *(uint32_t*)(H1 + baseA + px) =
            cvt_f16x2((acc1[nt][1] + b1A) * hscale, (acc1[nt][0] + b1A) * hscale);
        *(uint32_t*)(H1 + baseB + px) =
            cvt_f16x2((acc1[nt][3] + b1B) * hscale, (acc1[nt][2] + b1B) * hscale);
        if (DUAL) {
            *(uint32_t*)(H2 + baseA + px) =
                cvt_f16x2(acc2[nt][1] + b2A, acc2[nt][0] + b2A);
            *(uint32_t*)(H2 + baseB + px) =
                cvt_f16x2(acc2[nt][3] + b2B, acc2[nt][2] + b2B);
        }
    }
}

// ================================================================
// output conv: hi-only fp16 X + residual (kept from R14: ~2.5us cheaper,
// rel_err impact 7.5e-6 -> 9.0e-6 only).
// ================================================================
__global__ __launch_bounds__(256) void conv_out(
    const float* __restrict__ X,
    const float* __restrict__ W1, const float* __restrict__ b1,
    float* __restrict__ Y1, const float* __restrict__ resid) {
    __shared__ __align__(16) char sbufc[34816];
    const int tid = threadIdx.x;
    const int lane = tid & 31;
    const int w = tid >> 5;
    const int bb = blockIdx.y;
    const int p0 = blockIdx.x * 32;
    const uint32_t sb = smem_u32(sbufc);
    const int brow = (lane & 7) + ((lane & 16) >> 1);
    const int bcol8 = (lane & 8) ? 8 : 0;

    float4 xreg[4];
#pragma unroll
    for (int i = 0; i < 4; i++) {
        int idx = i * 256 + tid;
        int ci = idx >> 3, px = (idx & 7) * 4;
        xreg[i] = *(const float4*)(X + ((size_t)bb * CC + ci) * HW + p0 + px);
    }

    uint32_t wa1[8][4];
    {
#pragma unroll
        for (int i = 0; i < 16; i++) {
            int idx = i * 256 + tid;
            int co = idx >> 5, ci = (idx & 31) * 4;
            float4 v = *(const float4*)(W1 + co * CC + ci);
            __half* d = (__half*)(sbufc) + co * 136 + ci;
            d[0] = __float2half(v.x); d[1] = __float2half(v.y);
            d[2] = __float2half(v.z); d[3] = __float2half(v.w);
        }
        __syncthreads();
        int row = w * 16 + (lane & 15);
        int colb = (lane >> 4) * 8;
#pragma unroll
        for (int ks = 0; ks < 8; ks++)
            ldsm4(wa1[ks], sb + (row * 136 + ks * 16 + colb) * 2);
        __syncthreads();
    }

#pragma unroll
    for (int i = 0; i < 4; i++) {
        int idx = i * 256 + tid;
        int ci = idx >> 3, px = (idx & 7) * 4;
        float vv[4] = { xreg[i].x, xreg[i].y, xreg[i].z, xreg[i].w };
#pragma unroll
        for (int j = 0; j < 4; j++)
            *((__half*)(sbufc) + (px + j) * 136 + ci) = __float2half(vv[j]);
    }
    __syncthreads();

    float acc1[4][4];
#pragma unroll
    for (int nt = 0; nt < 4; nt++)
#pragma unroll
        for (int i = 0; i < 4; i++) acc1[nt][i] = 0.0f;

#pragma unroll
    for (int ks = 0; ks < 8; ks++) {
#pragma unroll
        for (int n0 = 0; n0 < 2; n0++) {
            uint32_t bh[4];
            ldsm4(bh, sb + ((n0 * 16 + brow) * 136 + ks * 16 + bcol8) * 2);
            mma16816(acc1[n0 * 2], wa1[ks], bh);
            mma16816(acc1[n0 * 2 + 1], wa1[ks], bh + 2);
        }
    }

    int coA = w * 16 + (lane >> 2);
    int coB = coA + 8;
    float b1A = b1[coA], b1B = b1[coB];
    size_t baseA = ((size_t)bb * CC + coA) * HW + p0;
    size_t baseB = ((size_t)bb * CC + coB) * HW + p0;
#pragma unroll
    for (int nt = 0; nt < 4; nt++) {
        int px = nt * 8 + 2 * (lane & 3);
        float2 rA = *(const float2*)(resid + baseA + px);
        float2 rB = *(const float2*)(resid + baseB + px);
        *(float2*)(Y1 + baseA + px) =
            make_float2(acc1[nt][0] + b1A + rA.x, acc1[nt][1] + b1A + rA.y);
        *(float2*)(Y1 + baseB + px) =
            make_float2(acc1[nt][2] + b1B + rB.x, acc1[nt][3] + b1B + rB.y);
    }
}

// ================= fused mask convs, conv2 on packed FMA2 (unchanged) ========
__global__ __launch_bounds__(256) void mask_fused(const float* __restrict__ seg,
                                                  const float* __restrict__ Wm1,
                                                  const float* __restrict__ bm1,
                                                  const float* __restrict__ Wm2,
                                                  const float* __restrict__ bm2) {
    int y = blockIdx.x, b = blockIdx.y;
    __shared__ float sseg[5][66];
    __shared__ __align__(8) float2 smi[3][66][16];
    const float* sgb = seg + (size_t)b * HW;
    for (int i = threadIdx.x; i < 5 * 66; i += 256) {
        int r = i / 66, x = i % 66;
        int yy = y + r - 2, xx = x - 1;
        sseg[r][x] = (yy >= 0 && yy < 64 && xx >= 0 && xx < 64)
                     ? sgb[yy * 64 + xx] : 0.0f;
    }
    __syncthreads();
    for (int i = threadIdx.x; i < 32 * 3 * 66; i += 256) {
        int c = i / 198, rem = i % 198, r = rem / 66, x = rem % 66;
        int yy = y + r - 1, xx = x - 1;
        float v = 0.0f;
        if (yy >= 0 && yy < 64 && xx >= 0 && xx < 64) {
            float acc = bm1[c];
            const float* wp = Wm1 + c * 9;
#pragma unroll
            for (int dy = 0; dy < 3; dy++)
#pragma unroll
                for (int dx = 0; dx < 3; dx++)
                    acc += wp[dy * 3 + dx] * sseg[r + dy][x + dx - 1];
            v = fmaxf(acc, 0.0f);
        }
        ((float*)&smi[r][x][c >> 1])[c & 1] = v;
    }
    __syncthreads();

    int co = threadIdx.x >> 1;
    int xh = (threadIdx.x & 1) * 32;
    ull acc2[32];
    float bb = bm2[co];
#pragma unroll
    for (int p = 0; p < 32; p++) acc2[p] = pk2(bb, 0.0f);
    const float* wbase = Wm2 + co * 288;

    for (int c2 = 0; c2 < 16; c2++) {
#pragma unroll
        for (int r = 0; r < 3; r++) {
            ull rv[34];
#pragma unroll
            for (int t = 0; t < 34; t++)
                rv[t] = *(const ull*)&smi[r][xh + t][c2];
            const float* wp = wbase + (2 * c2) * 9 + r * 3;
            const float* wq = wp + 9;
#pragma unroll
            for (int dx = 0; dx < 3; dx++) {
                ull w2 = pk2(wp[dx], wq[dx]);
#pragma unroll
                for (int p = 0; p < 32; p++)
                    acc2[p] = fma2(w2, rv[p + dx], acc2[p]);
            }
        }
    }

    float* out = g_mf + ((size_t)b * CC + co) * HW + y * 64 + xh;
#pragma unroll
    for (int p = 0; p < 32; p++) {
        float lo, hi;
        upk2(acc2[p], lo, hi);
        out[p] = lo + hi;
    }
}

// ---------------- launch ----------------
extern "C" void kernel_launch(void* const* d_in, const int* in_sizes, int n_in,
                              void* d_out, int out_size) {
    const float* sr  = (const float*)d_in[0];
    const float* seg = (const float*)d_in[1];
    const float* Wq  = (const float*)d_in[2];
    const float* bq  = (const float*)d_in[3];
    const float* Wm1 = (const float*)d_in[4];
    const float* bm1 = (const float*)d_in[5];
    const float* Wm2 = (const float*)d_in[6];
    const float* bm2 = (const float*)d_in[7];
    const float* Wk  = (const float*)d_in[8];
    const float* bk  = (const float*)d_in[9];
    const float* Wv  = (const float*)d_in[10];
    const float* bv  = (const float*)d_in[11];
    const float* Wo  = (const float*)d_in[12];
    const float* bo  = (const float*)d_in[13];
    float* out = (float*)d_out;

    float *pmf, *pg;
    __half *pqh, *pkh, *pvh;
    cudaGetSymbolAddress((void**)&pmf, g_mf);
    cudaGetSymbolAddress((void**)&pg, g_gd);
    cudaGetSymbolAddress((void**)&pqh, g_qh);
    cudaGetSymbolAddress((void**)&pkh, g_kh);
    cudaGetSymbolAddress((void**)&pvh, g_vh);

    static cudaStream_t s2 = nullptr;
    static cudaEvent_t e0 = nullptr, e1 = nullptr;
    if (s2 == nullptr) {
        cudaStreamCreateWithFlags(&s2, cudaStreamNonBlocking);
        cudaEventCreateWithFlags(&e0, cudaEventDisableTiming);
        cudaEventCreateWithFlags(&e1, cudaEventDisableTiming);
    }

    cudaFuncSetAttribute(attn_mma, cudaFuncAttributeMaxDynamicSharedMemorySize,
                         SBUF_BYTES);
    cudaFuncSetAttribute(conv_in<true>,
                         cudaFuncAttributeMaxDynamicSharedMemorySize, 69632);

    cudaEventRecord(e0, 0);
    cudaStreamWaitEvent(s2, e0, 0);
    conv_in<false><<<dim3(HW / 32, BATCH), 256, 34816, s2>>>(
        sr, Wq, bq, pqh, SCALE2, nullptr, nullptr, nullptr);
    cudaEventRecord(e1, s2);

    mask_fused<<<dim3(64, BATCH), 256>>>(seg, Wm1, bm1, Wm2, bm2);
    conv_in<true><<<dim3(HW / 32, BATCH), 256, 69632>>>(
        pmf, Wk, bk, pkh, 1.0f, Wv, bv, pvh);

    cudaStreamWaitEvent(0, e1, 0);
    attn_mma<<<dim3(32, HEADS, BATCH), 256, SBUF_BYTES>>>();
    conv_out<<<dim3(HW / 32, BATCH), 256>>>(pg, Wo, bo, out, sr);
}

// round 16
// speedup vs baseline: 1.1164x; 1.0979x over previous
#include <cuda_runtime.h>
#include <cuda_fp16.h>
#include <cstdint>
#include <cstddef>

#define BATCH 2
#define CC 128
#define HW 4096
#define HEADS 4
// 32^-0.5 * log2(e): softmax in base-2
#define SCALE2 0.25500526764086436f

// ---------------- scratch ----------------
__device__ __align__(16) __half g_qh[BATCH * CC * HW];
__device__ __align__(16) __half g_kh[BATCH * CC * HW];
__device__ __align__(16) __half g_vh[BATCH * CC * HW];
__device__ __align__(16) __half g_gdh[BATCH * HW * CC];   // guided, pixel-major

// ---------------- helpers ----------------
typedef unsigned long long ull;
__device__ __forceinline__ ull pk2(float a, float b) {
    ull r; asm("mov.b64 %0, {%1, %2};" : "=l"(r) : "f"(a), "f"(b)); return r;
}
__device__ __forceinline__ void upk2(ull v, float& a, float& b) {
    asm("mov.b64 {%0, %1}, %2;" : "=f"(a), "=f"(b) : "l"(v));
}
__device__ __forceinline__ ull fma2(ull a, ull b, ull c) {
    ull d; asm("fma.rn.f32x2 %0, %1, %2, %3;" : "=l"(d) : "l"(a), "l"(b), "l"(c)); return d;
}
__device__ __forceinline__ uint32_t smem_u32(const void* p) {
    uint32_t a;
    asm("{ .reg .u64 t; cvta.to.shared.u64 t, %1; cvt.u32.u64 %0, t; }" : "=r"(a) : "l"(p));
    return a;
}
__device__ __forceinline__ float ex2f(float x) {
    float r; asm("ex2.approx.f32 %0, %1;" : "=f"(r) : "f"(x)); return r;
}
__device__ __forceinline__ uint32_t cvt_f16x2(float hi, float lo) {
    uint32_t r; asm("cvt.rn.f16x2.f32 %0, %1, %2;" : "=r"(r) : "f"(hi), "f"(lo)); return r;
}
__device__ __forceinline__ uint32_t ex2_h2(uint32_t a) {
    uint32_t r; asm("ex2.approx.f16x2 %0, %1;" : "=r"(r) : "r"(a)); return r;
}
__device__ __forceinline__ void ldsm4(uint32_t* r, uint32_t addr) {
    asm volatile("ldmatrix.sync.aligned.m8n8.x4.shared.b16 {%0,%1,%2,%3}, [%4];"
        : "=r"(r[0]), "=r"(r[1]), "=r"(r[2]), "=r"(r[3]) : "r"(addr));
}
__device__ __forceinline__ void ldsm4t(uint32_t* r, uint32_t addr) {
    asm volatile("ldmatrix.sync.aligned.m8n8.x4.trans.shared.b16 {%0,%1,%2,%3}, [%4];"
        : "=r"(r[0]), "=r"(r[1]), "=r"(r[2]), "=r"(r[3]) : "r"(addr));
}
__device__ __forceinline__ void mma16816(float* c, const uint32_t* a, const uint32_t* b) {
    asm volatile("mma.sync.aligned.m16n8k16.row.col.f32.f16.f16.f32 "
        "{%0,%1,%2,%3}, {%4,%5,%6,%7}, {%8,%9}, {%0,%1,%2,%3};"
        : "+f"(c[0]), "+f"(c[1]), "+f"(c[2]), "+f"(c[3])
        : "r"(a[0]), "r"(a[1]), "r"(a[2]), "r"(a[3]), "r"(b[0]), "r"(b[1]));
}
__device__ __forceinline__ void cp16(uint32_t saddr, const void* g) {
    asm volatile("cp.async.cg.shared.global [%0], [%1], 16;" :: "r"(saddr), "l"(g));
}
#define CP_COMMIT() asm volatile("cp.async.commit_group;" ::: "memory")
#define CP_WAIT1()  asm volatile("cp.async.wait_group 1;" ::: "memory")
#define CP_WAIT2()  asm volatile("cp.async.wait_group 2;" ::: "memory")

// ================================================================
// fused QKV: grid (64 rows, BATCH, 2). z=0: mask convs + K/V 1x1 conv
// for this row's 64 pixels (mask row held in smem as fp16 B-tile).
// z=1: Q 1x1 conv (pre-scaled) for the same 64 pixels.
// dynamic smem layout:
//   [0, 25344)        smi  (float2[3][66][16])           -- z=0 only
//   [25408, 42816)    X fp16 tile [64 px][136 ch]        -- both
//   [25408, 26728)    sseg (float[5][66]) overlaps X     -- z=0, dead early
//   [42816, 77632)    W1 fp16 [128 co][136 ci]
//   [77632, 112448)   W2 fp16                            -- z=0 only
// ================================================================
#define SMI_OFF 0
#define X_OFF 25408
#define SSEG_OFF 25408
#define WA_OFF 42816
#define WB_OFF 77632
#define QKV_SMEM 112448

__global__ __launch_bounds__(256) void qkv_fused(
    const float* __restrict__ sr, const float* __restrict__ seg,
    const float* __restrict__ Wm1, const float* __restrict__ bm1,
    const float* __restrict__ Wm2, const float* __restrict__ bm2,
    const float* __restrict__ Wq, const float* __restrict__ bq,
    const float* __restrict__ Wk, const float* __restrict__ bk,
    const float* __restrict__ Wv, const float* __restrict__ bv) {
    extern __shared__ __align__(16) char dsm[];
    const int tid = threadIdx.x;
    const int lane = tid & 31;
    const int w = tid >> 5;
    const int y = blockIdx.x, b = blockIdx.y;
    const bool isQ = (blockIdx.z == 1);
    const uint32_t sb = smem_u32(dsm);
    const int brow = (lane & 7) + ((lane & 16) >> 1);
    const int bcol8 = (lane & 8) ? 8 : 0;
    __half* hx = (__half*)(dsm + X_OFF);

    const float* W1 = isQ ? Wq : Wk;
    // ---- stage W1 (+W2) fp16 ----
#pragma unroll
    for (int i = 0; i < 16; i++) {
        int idx = i * 256 + tid;
        int co = idx >> 5, ci = (idx & 31) * 4;
        float4 v = *(const float4*)(W1 + co * CC + ci);
        __half* d = (__half*)(dsm + WA_OFF) + co * 136 + ci;
        d[0] = __float2half(v.x); d[1] = __float2half(v.y);
        d[2] = __float2half(v.z); d[3] = __float2half(v.w);
    }
    if (!isQ) {
#pragma unroll
        for (int i = 0; i < 16; i++) {
            int idx = i * 256 + tid;
            int co = idx >> 5, ci = (idx & 31) * 4;
            float4 v = *(const float4*)(Wv + co * CC + ci);
            __half* d = (__half*)(dsm + WB_OFF) + co * 136 + ci;
            d[0] = __float2half(v.x); d[1] = __float2half(v.y);
            d[2] = __float2half(v.z); d[3] = __float2half(v.w);
        }
    }

    if (isQ) {
        // ---- X tile from sr (fp32 -> fp16 hi) ----
#pragma unroll
        for (int i = 0; i < 8; i++) {
            int idx = i * 256 + tid;
            int ci = idx >> 4, pxq = (idx & 15) * 4;
            float4 v = *(const float4*)(sr + ((size_t)b * CC + ci) * HW + y * 64 + pxq);
            hx[(pxq + 0) * 136 + ci] = __float2half(v.x);
            hx[(pxq + 1) * 136 + ci] = __float2half(v.y);
            hx[(pxq + 2) * 136 + ci] = __float2half(v.z);
            hx[(pxq + 3) * 136 + ci] = __float2half(v.w);
        }
        __syncthreads();
    } else {
        // ---- mask conv1+conv2 producing fp16 X tile ----
        float* sseg = (float*)(dsm + SSEG_OFF);
        float2* smi = (float2*)(dsm + SMI_OFF);
        const float* sgb = seg + (size_t)b * HW;
        for (int i = tid; i < 5 * 66; i += 256) {
            int r = i / 66, x = i % 66;
            int yy = y + r - 2, xx = x - 1;
            sseg[r * 66 + x] = (yy >= 0 && yy < 64 && xx >= 0 && xx < 64)
                               ? sgb[yy * 64 + xx] : 0.0f;
        }
        __syncthreads();
        for (int i = tid; i < 32 * 3 * 66; i += 256) {
            int c = i / 198, rem = i % 198, r = rem / 66, x = rem % 66;
            int yy = y + r - 1, xx = x - 1;
            float v = 0.0f;
            if (yy >= 0 && yy < 64 && xx >= 0 && xx < 64) {
                float acc = bm1[c];
                const float* wp = Wm1 + c * 9;
#pragma unroll
                for (int dy = 0; dy < 3; dy++)
#pragma unroll
                    for (int dx = 0; dx < 3; dx++)
                        acc += wp[dy * 3 + dx] * sseg[(r + dy) * 66 + x + dx - 1];
                v = fmaxf(acc, 0.0f);
            }
            ((float*)&smi[(r * 66 + x) * 16 + (c >> 1)])[c & 1] = v;
        }
        __syncthreads();

        int co = tid >> 1;
        int xh = (tid & 1) * 32;
        ull acc2[32];
        float bb = bm2[co];
#pragma unroll
        for (int p = 0; p < 32; p++) acc2[p] = pk2(bb, 0.0f);
        const float* wbase = Wm2 + co * 288;
        for (int c2 = 0; c2 < 16; c2++) {
#pragma unroll
            for (int r = 0; r < 3; r++) {
                ull rv[34];
#pragma unroll
                for (int t = 0; t < 34; t++)
                    rv[t] = *(const ull*)&smi[(r * 66 + xh + t) * 16 + c2];
                const float* wp = wbase + (2 * c2) * 9 + r * 3;
                const float* wq = wp + 9;
#pragma unroll
                for (int dx = 0; dx < 3; dx++) {
                    ull w2 = pk2(wp[dx], wq[dx]);
#pragma unroll
                    for (int p = 0; p < 32; p++)
                        acc2[p] = fma2(w2, rv[p + dx], acc2[p]);
                }
            }
        }
#pragma unroll
        for (int p = 0; p < 32; p++) {
            float lo, hi;
            upk2(acc2[p], lo, hi);
            hx[(xh + p) * 136 + co] = __float2half(lo + hi);
        }
        __syncthreads();   // X + W stores visible
    }

    // ---- W A-fragments ----
    uint32_t wa1[8][4], wa2[8][4];
    {
        int row = w * 16 + (lane & 15);
        int colb = (lane >> 4) * 8;
#pragma unroll
        for (int ks = 0; ks < 8; ks++) {
            ldsm4(wa1[ks], sb + WA_OFF + (row * 136 + ks * 16 + colb) * 2);
            if (!isQ)
                ldsm4(wa2[ks], sb + WB_OFF + (row * 136 + ks * 16 + colb) * 2);
        }
    }

    const float hscale = isQ ? SCALE2 : 1.0f;
    const float* b1 = isQ ? bq : bk;
    __half* H1 = isQ ? g_qh : g_kh;
    int coA = w * 16 + (lane >> 2);
    int coB = coA + 8;
    float b1A = b1[coA], b1B = b1[coB];
    float b2A = 0.0f, b2B = 0.0f;
    if (!isQ) { b2A = bv[coA]; b2B = bv[coB]; }

    // ---- MMA over 64 pixels in two 32-px halves ----
#pragma unroll
    for (int half = 0; half < 2; half++) {
        float acc1[4][4], acc2m[4][4];
#pragma unroll
        for (int nt = 0; nt < 4; nt++)
#pragma unroll
            for (int i = 0; i < 4; i++) { acc1[nt][i] = 0.0f; acc2m[nt][i] = 0.0f; }
#pragma unroll
        for (int ks = 0; ks < 8; ks++) {
#pragma unroll
            for (int n0 = 0; n0 < 2; n0++) {
                uint32_t bh[4];
                ldsm4(bh, sb + X_OFF +
                      ((half * 32 + n0 * 16 + brow) * 136 + ks * 16 + bcol8) * 2);
                mma16816(acc1[n0 * 2], wa1[ks], bh);
                mma16816(acc1[n0 * 2 + 1], wa1[ks], bh + 2);
                if (!isQ) {
                    mma16816(acc2m[n0 * 2], wa2[ks], bh);
                    mma16816(acc2m[n0 * 2 + 1], wa2[ks], bh + 2);
                }
            }
        }
        size_t baseA = ((size_t)b * CC + coA) * HW + y * 64 + half * 32;
        size_t baseB = ((size_t)b * CC + coB) * HW + y * 64 + half * 32;
#pragma unroll
        for (int nt = 0; nt < 4; nt++) {
            int px = nt * 8 + 2 * (lane & 3);
            *(uint32_t*)(H1 + baseA + px) =
                cvt_f16x2((acc1[nt][1] + b1A) * hscale, (acc1[nt][0] + b1A) * hscale);
            *(uint32_t*)(H1 + baseB + px) =
                cvt_f16x2((acc1[nt][3] + b1B) * hscale, (acc1[nt][2] + b1B) * hscale);
            if (!isQ) {
                *(uint32_t*)(g_vh + baseA + px) =
                    cvt_f16x2(acc2m[nt][1] + b2A, acc2m[nt][0] + b2A);
                *(uint32_t*)(g_vh + baseB + px) =
                    cvt_f16x2(acc2m[nt][3] + b2B, acc2m[nt][2] + b2B);
            }
        }
    }
}

// ================================================================
// flash attention (R13 core): fp16 QK/PV, lazy-max softmax, l via
// ones-column MMA, cross-tile pipeline, 4-stage cp.async ring.
// Epilogue writes fp16 pixel-major g_gdh.
// ================================================================
#define STAGE 17408
#define NSTAGE 4
#define SB_Q (NSTAGE * STAGE)
#define SBUF_BYTES (SB_Q + 8704)

__global__ void __launch_bounds__(256, 2) attn_mma() {
    extern __shared__ __align__(16) char sbuf[];
    const int tid = threadIdx.x;
    const int lane = tid & 31;
    const int w = tid >> 5;
    const int h = blockIdx.y, b = blockIdx.z;
    const int qb = blockIdx.x * 128;
    const size_t cbase = ((size_t)b * CC + h * 32) * HW;
    const __half* qgp = g_qh + cbase;
    const __half* kgp = g_kh + cbase;
    const __half* vgp = g_vh + cbase;
    const uint32_t sb = smem_u32(sbuf);

    const int cd = tid >> 3;
    const int cjh = (tid & 7) * 16;
    const uint32_t offK = (uint32_t)(cd * 136 + cjh) * 2;
    const uint32_t offV = 8704u + offK;
    const __half* gQ = qgp + (size_t)cd * HW + qb + cjh;
    const __half* gK = kgp + (size_t)cd * HW + cjh;
    const __half* gV = vgp + (size_t)cd * HW + cjh;
    cp16(sb + SB_Q + offK, gQ); cp16(sb + SB_Q + offK + 16, gQ + 8);
    CP_COMMIT();
    cp16(sb + offK, gK);       cp16(sb + offK + 16, gK + 8);
    cp16(sb + offV, gV);       cp16(sb + offV + 16, gV + 8);
    CP_COMMIT();
    cp16(sb + STAGE + offK, gK + 128); cp16(sb + STAGE + offK + 16, gK + 136);
    cp16(sb + STAGE + offV, gV + 128); cp16(sb + STAGE + offV + 16, gV + 136);
    CP_COMMIT();

    const int brow = (lane & 7) + ((lane & 16) >> 1);
    const int bcol8 = (lane & 8) ? 8 : 0;

    CP_WAIT2();
    __syncthreads();
    uint32_t qa[2][4];
#pragma unroll
    for (int ks = 0; ks < 2; ks++)
        ldsm4t(qa[ks], sb + SB_Q + ((ks * 16 + brow) * 136 + w * 16 + bcol8) * 2);

    const uint32_t b2c[2] = { (lane < 4) ? 0x3C003C00u : 0u,
                              (lane < 4) ? 0x3C003C00u : 0u };

    float mrow0 = 0.0f, mrow1 = 0.0f;
    float o[4][4], ol[4];
#pragma unroll
    for (int nt = 0; nt < 4; nt++)
#pragma unroll
        for (int i = 0; i < 4; i++) o[nt][i] = 0.0f;
#pragma unroll
    for (int i = 0; i < 4; i++) ol[i] = 0.0f;

    float s[8][4];
    uint32_t pu[8][2];

    auto s_init = [&]() {
        float ns0 = -mrow0, ns1 = -mrow1;
#pragma unroll
        for (int nt = 0; nt < 8; nt++) {
            s[nt][0] = ns0; s[nt][1] = ns0;
            s[nt][2] = ns1; s[nt][3] = ns1;
        }
    };
    auto qk_piece = [&](uint32_t base, int idx, int joff) {
        int ks = idx >> 2, n0 = idx & 3;
        uint32_t bh[4];
        ldsm4t(bh, base + ((ks * 16 + (lane & 15)) * 136 +
                           joff + n0 * 16 + (lane >> 4) * 8) * 2);
        mma16816(s[n0 * 2], qa[ks], bh);
        mma16816(s[n0 * 2 + 1], qa[ks], bh + 2);
    };
    auto pv_piece = [&](uint32_t base, int ks, int joff) {
        uint32_t ah[4] = { pu[2 * ks][0], pu[2 * ks][1],
                           pu[2 * ks + 1][0], pu[2 * ks + 1][1] };
#pragma unroll
        for (int n0 = 0; n0 < 2; n0++) {
            uint32_t vh[4];
            ldsm4(vh, base + 8704 + ((n0 * 16 + brow) * 136 +
                                     joff + ks * 16 + bcol8) * 2);
            mma16816(o[n0 * 2], ah, vh);
            mma16816(o[n0 * 2 + 1], ah, vh + 2);
        }
        mma16816(ol, ah, b2c);
    };
    auto softmax = [&]() {
        float mt0 = s[0][0], mt1 = s[0][2];
#pragma unroll
        for (int nt = 0; nt < 8; nt++) {
            mt0 = fmaxf(mt0, fmaxf(s[nt][0], s[nt][1]));
            mt1 = fmaxf(mt1, fmaxf(s[nt][2], s[nt][3]));
        }
        if (__any_sync(0xffffffffu, fmaxf(mt0, mt1) > 8.0f)) {
            mt0 = fmaxf(mt0, __shfl_xor_sync(0xffffffffu, mt0, 1));
            mt0 = fmaxf(mt0, __shfl_xor_sync(0xffffffffu, mt0, 2));
            mt1 = fmaxf(mt1, __shfl_xor_sync(0xffffffffu, mt1, 1));
            mt1 = fmaxf(mt1, __shfl_xor_sync(0xffffffffu, mt1, 2));
            float d0 = fmaxf(mt0, 0.0f), d1 = fmaxf(mt1, 0.0f);
            float c0 = ex2f(-d0), c1 = ex2f(-d1);
            mrow0 += d0; mrow1 += d1;
#pragma unroll
            for (int nt = 0; nt < 4; nt++) {
                o[nt][0] *= c0; o[nt][1] *= c0;
                o[nt][2] *= c1; o[nt][3] *= c1;
            }
            ol[0] *= c0; ol[1] *= c0; ol[2] *= c1; ol[3] *= c1;
#pragma unroll
            for (int nt = 0; nt < 8; nt++) {
                s[nt][0] -= d0; s[nt][1] -= d0;
                s[nt][2] -= d1; s[nt][3] -= d1;
            }
        }
#pragma unroll
        for (int nt = 0; nt < 8; nt++) {
            pu[nt][0] = ex2_h2(cvt_f16x2(s[nt][1], s[nt][0]));
            pu[nt][1] = ex2_h2(cvt_f16x2(s[nt][3], s[nt][2]));
        }
    };

    CP_WAIT1();
    __syncthreads();
    s_init();
#pragma unroll
    for (int i = 0; i < 8; i++) qk_piece(sb, i, 0);

#pragma unroll 4
    for (int t = 0; t < 32; t++) {
        const uint32_t bcur = sb + (uint32_t)(t & 3) * STAGE;
        const uint32_t bnxt = sb + (uint32_t)((t + 1) & 3) * STAGE;

        softmax();
        s_init();
#pragma unroll
        for (int ks = 0; ks < 4; ks++) {
            pv_piece(bcur, ks, 0);
            qk_piece(bcur, 2 * ks, 64);
            qk_piece(bcur, 2 * ks + 1, 64);
        }
        softmax();

        if (t + 2 < 32) {
            const uint32_t so = sb + (uint32_t)((t + 2) & 3) * STAGE;
            const int go = (t + 2) * 128;
            cp16(so + offK, gK + go);       cp16(so + offK + 16, gK + go + 8);
            cp16(so + offV, gV + go);       cp16(so + offV + 16, gV + go + 8);
        }
        CP_COMMIT();
        CP_WAIT1();
        __syncthreads();

        if (t < 31) {
            s_init();
#pragma unroll
            for (int ks = 0; ks < 4; ks++) {
                pv_piece(bcur, ks, 64);
                qk_piece(bnxt, 2 * ks, 0);
                qk_piece(bnxt, 2 * ks + 1, 0);
            }
        } else {
#pragma unroll
            for (int ks = 0; ks < 4; ks++) pv_piece(bcur, ks, 64);
        }
    }

    // ---------------- finalize: fp16 pixel-major ----------------
    float l0 = __shfl_sync(0xffffffffu, ol[0], lane & 28);
    float l1 = __shfl_sync(0xffffffffu, ol[2], lane & 28);
    float i0 = 1.0f / l0, i1 = 1.0f / l1;
    int pix = qb + w * 16 + (lane >> 2);
    __half* og = g_gdh + ((size_t)b * HW + pix) * CC + h * 32;
#pragma unroll
    for (int nt = 0; nt < 4; nt++) {
        int d = nt * 8 + 2 * (lane & 3);
        *(uint32_t*)(og + d) = cvt_f16x2(o[nt][1] * i0, o[nt][0] * i0);
        *(uint32_t*)(og + 8 * CC + d) = cvt_f16x2(o[nt][3] * i1, o[nt][2] * i1);
    }
}

// ================================================================
// output conv: fp16 pixel-major X (no cvt staging) + residual.
// ================================================================
__global__ __launch_bounds__(256) void conv_out(
    const __half* __restrict__ X,
    const float* __restrict__ W1, const float* __restrict__ b1,
    float* __restrict__ Y1, const float* __restrict__ resid) {
    __shared__ __align__(16) char sbufc[34816];
    const int tid = threadIdx.x;
    const int lane = tid & 31;
    const int w = tid >> 5;
    const int bb = blockIdx.y;
    const int p0 = blockIdx.x * 32;
    const uint32_t sb = smem_u32(sbufc);
    const int brow = (lane & 7) + ((lane & 16) >> 1);
    const int bcol8 = (lane & 8) ? 8 : 0;

    // X staging: pure uint4 copies (issued first)
    uint4 xreg[2];
#pragma unroll
    for (int i = 0; i < 2; i++) {
        int idx = i * 256 + tid;
        int px = idx >> 4, c16 = (idx & 15) * 8;
        xreg[i] = *(const uint4*)(X + ((size_t)bb * HW + p0 + px) * CC + c16);
    }

    uint32_t wa1[8][4];
    {
#pragma unroll
        for (int i = 0; i < 16; i++) {
            int idx = i * 256 + tid;
            int co = idx >> 5, ci = (idx & 31) * 4;
            float4 v = *(const float4*)(W1 + co * CC + ci);
            __half* d = (__half*)(sbufc) + co * 136 + ci;
            d[0] = __float2half(v.x); d[1] = __float2half(v.y);
            d[2] = __float2half(v.z); d[3] = __float2half(v.w);
        }
        __syncthreads();
        int row = w * 16 + (lane & 15);
        int colb = (lane >> 4) * 8;
#pragma unroll
        for (int ks = 0; ks < 8; ks++)
            ldsm4(wa1[ks], sb + (row * 136 + ks * 16 + colb) * 2);
        __syncthreads();
    }

#pragma unroll
    for (int i = 0; i < 2; i++) {
        int idx = i * 256 + tid;
        int px = idx >> 4, c16 = (idx & 15) * 8;
        *(uint4*)((__half*)(sbufc) + px * 136 + c16) = xreg[i];
    }
    __syncthreads();

    float acc1[4][4];
#pragma unroll
    for (int nt = 0; nt < 4; nt++)
#pragma unroll
        for (int i = 0; i < 4; i++) acc1[nt][i] = 0.0f;

#pragma unroll
    for (int ks = 0; ks < 8; ks++) {
#pragma unroll
        for (int n0 = 0; n0 < 2; n0++) {
            uint32_t bh[4];
            ldsm4(bh, sb + ((n0 * 16 + brow) * 136 + ks * 16 + bcol8) * 2);
            mma16816(acc1[n0 * 2], wa1[ks], bh);
            mma16816(acc1[n0 * 2 + 1], wa1[ks], bh + 2);
        }
    }

    int coA = w * 16 + (lane >> 2);
    int coB = coA + 8;
    float b1A = b1[coA], b1B = b1[coB];
    size_t baseA = ((size_t)bb * CC + coA) * HW + p0;
    size_t baseB = ((size_t)bb * CC + coB) * HW + p0;
#pragma unroll
    for (int nt = 0; nt < 4; nt++) {
        int px = nt * 8 + 2 * (lane & 3);
        float2 rA = *(const float2*)(resid + baseA + px);
        float2 rB = *(const float2*)(resid + baseB + px);
        *(float2*)(Y1 + baseA + px) =
            make_float2(acc1[nt][0] + b1A + rA.x, acc1[nt][1] + b1A + rA.y);
        *(float2*)(Y1 + baseB + px) =
            make_float2(acc1[nt][2] + b1B + rB.x, acc1[nt][3] + b1B + rB.y);
    }
}

// ---------------- launch ----------------
extern "C" void kernel_launch(void* const* d_in, const int* in_sizes, int n_in,
                              void* d_out, int out_size) {
    const float* sr  = (const float*)d_in[0];
    const float* seg = (const float*)d_in[1];
    const float* Wq  = (const float*)d_in[2];
    const float* bq  = (const float*)d_in[3];
    const float* Wm1 = (const float*)d_in[4];
    const float* bm1 = (const float*)d_in[5];
    const float* Wm2 = (const float*)d_in[6];
    const float* bm2 = (const float*)d_in[7];
    const float* Wk  = (const float*)d_in[8];
    const float* bk  = (const float*)d_in[9];
    const float* Wv  = (const float*)d_in[10];
    const float* bv  = (const float*)d_in[11];
    const float* Wo  = (const float*)d_in[12];
    const float* bo  = (const float*)d_in[13];
    float* out = (float*)d_out;

    __half* pgdh;
    cudaGetSymbolAddress((void**)&pgdh, g_gdh);

    cudaFuncSetAttribute(attn_mma, cudaFuncAttributeMaxDynamicSharedMemorySize,
                         SBUF_BYTES);
    cudaFuncSetAttribute(qkv_fused, cudaFuncAttributeMaxDynamicSharedMemorySize,
                         QKV_SMEM);

    qkv_fused<<<dim3(64, BATCH, 2), 256, QKV_SMEM>>>(
        sr, seg, Wm1, bm1, Wm2, bm2, Wq, bq, Wk, bk, Wv, bv);
    attn_mma<<<dim3(32, HEADS, BATCH), 256, SBUF_BYTES>>>();
    conv_out<<<dim3(HW / 32, BATCH), 256>>>(pgdh, Wo, bo, out, sr);
}